// round 15
// baseline (speedup 1.0000x reference)
#include <cuda_runtime.h>
#include <cuda_bf16.h>
#include <cstdint>

#define B_ 16384
#define K_ 5
#define D_ 512
#define HG_ 16

// ---------------- scratch (static device globals; no allocs allowed) --------
__device__ __nv_bfloat16 g_xh[B_ * D_],  g_xl[B_ * D_];        // x (merge input)
__device__ __nv_bfloat16 g_iah[B_ * D_], g_ial[B_ * D_];       // image split
__device__ __nv_bfloat16 g_fh[B_ * D_],  g_fl[B_ * D_];        // fused
__device__ __nv_bfloat16 g_uh[2 * B_ * D_], g_ul[2 * B_ * D_]; // u stacked
__device__ float  g_v[2 * B_ * D_];
__device__ double g_sum[5 * D_];
__device__ double g_sq[5 * D_];
__device__ float  g_scl[5 * D_];
__device__ float  g_sft[5 * D_];
// scl-folded W^T hi/lo bf16 [n][k], 5 slots: 0=mg 1=ph1/img 2=ph1/fused 3=ph2/img 4=ph2/fused
__device__ __nv_bfloat16 g_wh[5 * D_ * D_], g_wl[5 * D_ * D_];
__device__ float g_bb[5 * D_];   // bias + sft@W per slot

__device__ __forceinline__ float gelu_tanh(float x) {
    float x3 = x * x * x;
    float t  = tanhf(0.7978845608028654f * (x + 0.044715f * x3));
    return 0.5f * x * (1.0f + t);
}

// --- bitwise replication of XLA:CPU's vectorized f32 exp (Cephes expf) ------
__device__ __forceinline__ float xla_expf(float x) {
    float xx = fminf(fmaxf(x, -88.3762626647949f), 88.3762626647950f);
    float z  = floorf(__fadd_rn(__fmul_rn(1.44269504088896341f, xx), 0.5f));
    xx = __fsub_rn(xx, __fmul_rn(z, 0.693359375f));
    xx = __fsub_rn(xx, __fmul_rn(z, -2.12194440e-4f));
    float x2 = __fmul_rn(xx, xx);
    float y  = 1.9875691500E-4f;
    y = __fadd_rn(__fmul_rn(y, xx), 1.3981999507E-3f);
    y = __fadd_rn(__fmul_rn(y, xx), 8.3334519073E-3f);
    y = __fadd_rn(__fmul_rn(y, xx), 4.1665795894E-2f);
    y = __fadd_rn(__fmul_rn(y, xx), 1.6666665459E-1f);
    y = __fadd_rn(__fmul_rn(y, xx), 5.0000001201E-1f);
    y = __fadd_rn(__fmul_rn(y, x2), xx);
    y = __fadd_rn(y, 1.0f);
    return ldexpf(y, (int)z);
}
__device__ __forceinline__ float xla_sigmoid(float x) {
    return __fdiv_rn(1.0f, __fadd_rn(1.0f, xla_expf(-x)));
}

// mma.sync m16n8k16 bf16: D(f32) += A(bf16,row) * B(bf16,col)
__device__ __forceinline__ void mma_bf16(float* d, const uint32_t* a,
                                         uint32_t b0, uint32_t b1) {
    asm volatile(
        "mma.sync.aligned.m16n8k16.row.col.f32.bf16.bf16.f32 "
        "{%0,%1,%2,%3}, {%4,%5,%6,%7}, {%8,%9}, {%0,%1,%2,%3};"
        : "+f"(d[0]), "+f"(d[1]), "+f"(d[2]), "+f"(d[3])
        : "r"(a[0]), "r"(a[1]), "r"(a[2]), "r"(a[3]), "r"(b0), "r"(b1));
}
__device__ __forceinline__ void ldm_x4(uint32_t* r, uint32_t addr) {
    asm volatile("ldmatrix.sync.aligned.m8n8.x4.shared.b16 {%0,%1,%2,%3}, [%4];"
                 : "=r"(r[0]), "=r"(r[1]), "=r"(r[2]), "=r"(r[3]) : "r"(addr));
}
__device__ __forceinline__ uint32_t smem_a32(const void* p) {
    return (uint32_t)__cvta_generic_to_shared(p);
}
__device__ __forceinline__ void cp16(uint32_t dst, const void* src) {
    asm volatile("cp.async.ca.shared.global [%0], [%1], 16;" :: "r"(dst), "l"(src));
}
__device__ __forceinline__ void cp_commit() { asm volatile("cp.async.commit_group;"); }
__device__ __forceinline__ void cp_wait0()  { asm volatile("cp.async.wait_group 0;" ::: "memory"); }

// ---------------------------------------------------------------------------
__global__ void zero_stats_k() {
    int i = blockIdx.x * blockDim.x + threadIdx.x;
    if (i < 5 * D_) { g_sum[i] = 0.0; g_sq[i] = 0.0; }
}

// fp32 array -> bf16 hi/lo split (used for image)
__global__ void split_k(const float* __restrict__ X,
                        __nv_bfloat16* __restrict__ H, __nv_bfloat16* __restrict__ L) {
    int i = blockIdx.x * blockDim.x + threadIdx.x;
    float v = X[i];
    __nv_bfloat16 h = __float2bfloat16(v);
    H[i] = h;
    L[i] = __float2bfloat16(v - __bfloat162float(h));
}

// W [k][n] fp32 * scl[k] -> W'^T hi/lo bf16 [n][k]
__global__ void wconv_k(const float* __restrict__ W, const float* __restrict__ scl,
                        __nv_bfloat16* __restrict__ WH, __nv_bfloat16* __restrict__ WL) {
    int idx = blockIdx.x * blockDim.x + threadIdx.x;
    int n = idx >> 9, k = idx & 511;
    float v = W[k * D_ + n] * scl[k];
    __nv_bfloat16 h = __float2bfloat16(v);
    WH[idx] = h;
    WL[idx] = __float2bfloat16(v - __bfloat162float(h));
}

// outb[n] = bias[n] + sum_k sft[k] * W[k][n]
__global__ void biasfix_k(const float* __restrict__ W, const float* __restrict__ bias,
                          const float* __restrict__ sft, float* __restrict__ outb) {
    int n = threadIdx.x;
    float s = bias[n];
    for (int k = 0; k < D_; k++) s = fmaf(sft[k], W[k * D_ + n], s);
    outb[n] = s;
}

__global__ void row_kernel(const float* __restrict__ img, const float* __restrict__ txt,
                           const float* __restrict__ w1, const float* __restrict__ b1,
                           const float* __restrict__ w2, const float* __restrict__ b2,
                           const float* __restrict__ cw, const float* __restrict__ cb)
{
    int w    = (blockIdx.x * blockDim.x + threadIdx.x) >> 5;
    int lane = threadIdx.x & 31;
    if (w >= B_) return;

    const float* ip = img + (size_t)w * D_;
    float  iv[16];
    double isq = 0.0;
#pragma unroll
    for (int i = 0; i < 16; i++) {
        iv[i] = ip[lane + 32 * i];
        isq += (double)iv[i] * (double)iv[i];
    }
#pragma unroll
    for (int o = 16; o; o >>= 1) isq += __shfl_xor_sync(0xffffffffu, isq, o);
    float inorm = fmaxf(sqrtf((float)isq), 1e-12f);

    float ivn[16];
#pragma unroll
    for (int i = 0; i < 16; i++) ivn[i] = __fdiv_rn(iv[i], inorm);

    float tv[K_][16];
    float sim[K_];
#pragma unroll
    for (int k = 0; k < K_; k++) {
        const float* tp = txt + ((size_t)w * K_ + k) * D_;
        double tsq = 0.0;
#pragma unroll
        for (int i = 0; i < 16; i++) {
            float t  = tp[lane + 32 * i];
            tv[k][i] = t;
            tsq += (double)t * (double)t;
        }
#pragma unroll
        for (int o = 16; o; o >>= 1) tsq += __shfl_xor_sync(0xffffffffu, tsq, o);
        float tnorm = fmaxf(sqrtf((float)tsq), 1e-12f);

        double dot = 0.0;
#pragma unroll
        for (int i = 0; i < 16; i++) {
            float tn = __fdiv_rn(tv[k][i], tnorm);
            dot += (double)__fmul_rn(ivn[i], tn);
        }
#pragma unroll
        for (int o = 16; o; o >>= 1) dot += __shfl_xor_sync(0xffffffffu, dot, o);
        sim[k] = (float)dot;
    }

    float wt[K_];
#pragma unroll
    for (int k = 0; k < K_; k++) {
        float acc = 0.0f;
#pragma unroll
        for (int j = 0; j < HG_; j++) {
            float h = fmaxf(__fadd_rn(__fmul_rn(sim[k], w1[j]), b1[j]), 0.0f);
            acc = __fadd_rn(acc, __fmul_rn(h, w2[j]));
        }
        acc   = __fadd_rn(acc, b2[0]);
        wt[k] = xla_sigmoid(acc);
    }

    float coef[K_];
#pragma unroll
    for (int p = 0; p < K_; p++) {
        int r = 0;
#pragma unroll
        for (int q = 0; q < K_; q++)
            r += (wt[q] > wt[p]) || (wt[q] == wt[p] && q < p);
        coef[p] = cw[r] * wt[p];
    }

    float cbv = cb[0];
#pragma unroll
    for (int i = 0; i < 16; i++) {
        float s = cbv;
#pragma unroll
        for (int p = 0; p < K_; p++) s = fmaf(coef[p], tv[p][i], s);
        size_t idx = (size_t)w * D_ + lane + 32 * i;
        __nv_bfloat16 h = __float2bfloat16(s);
        g_xh[idx] = h;
        g_xl[idx] = __float2bfloat16(s - __bfloat162float(h));
    }
}

// fp32 column stats (image input only)
__global__ void colstats_k(const float* __restrict__ A, int rows, int set) {
    int c     = threadIdx.x;
    int chunk = rows / gridDim.x;
    const float* p = A + (size_t)blockIdx.x * chunk * D_ + c;
    float s0 = 0.f, s1 = 0.f, q0 = 0.f, q1 = 0.f;
#pragma unroll 8
    for (int r = 0; r < chunk; r += 2) {
        float v0 = p[(size_t)r * D_];
        float v1 = p[(size_t)(r + 1) * D_];
        s0 += v0; q0 = fmaf(v0, v0, q0);
        s1 += v1; q1 = fmaf(v1, v1, q1);
    }
    atomicAdd(&g_sum[set * D_ + c], (double)(s0 + s1));
    atomicAdd(&g_sq[set * D_ + c], (double)(q0 + q1));
}

// hi/lo column stats (v = hi + lo)
__global__ void colstats_hl(const __nv_bfloat16* __restrict__ H,
                            const __nv_bfloat16* __restrict__ L, int rows, int set) {
    int c     = threadIdx.x;
    int chunk = rows / gridDim.x;
    size_t base = (size_t)blockIdx.x * chunk * D_ + c;
    float s0 = 0.f, s1 = 0.f, q0 = 0.f, q1 = 0.f;
#pragma unroll 8
    for (int r = 0; r < chunk; r += 2) {
        float v0 = __bfloat162float(H[base + (size_t)r * D_]) +
                   __bfloat162float(L[base + (size_t)r * D_]);
        float v1 = __bfloat162float(H[base + (size_t)(r + 1) * D_]) +
                   __bfloat162float(L[base + (size_t)(r + 1) * D_]);
        s0 += v0; q0 = fmaf(v0, v0, q0);
        s1 += v1; q1 = fmaf(v1, v1, q1);
    }
    atomicAdd(&g_sum[set * D_ + c], (double)(s0 + s1));
    atomicAdd(&g_sq[set * D_ + c], (double)(q0 + q1));
}

__global__ void finalize_k(int set, const float* __restrict__ g, const float* __restrict__ b,
                           float inv) {
    int   c    = threadIdx.x;
    float mean = (float)(g_sum[set * D_ + c] * inv);
    float ex2  = (float)(g_sq[set * D_ + c] * inv);
    float var  = ex2 - mean * mean;
    float sc   = g[c] * rsqrtf(var + 1e-5f);
    g_scl[set * D_ + c] = sc;
    g_sft[set * D_ + c] = b[c] - mean * sc;
}

// ---------------- tensor-core GEMM: C = act( A @ W' + b' ) ------------------
// A and W' pre-split bf16 hi/lo in global. Staging = pure cp.async copies,
// double-buffered. CTA 128x128, 256 thr = 8 warps (4M x 2N), BK=32.
// mode 1: gelu + write hi/lo bf16. mode 0: write fp32.
#define ST_ 40
#define STAGE_BYTES (4 * 128 * ST_ * 2)   // 40960
#define GEMM_DSMEM  (2 * STAGE_BYTES)

__global__ __launch_bounds__(256) void gemm_mma(
    const __nv_bfloat16* __restrict__ A0h, const __nv_bfloat16* __restrict__ A0l,
    const __nv_bfloat16* __restrict__ A1h, const __nv_bfloat16* __restrict__ A1l,
    int splitM,
    const __nv_bfloat16* __restrict__ W0h, const __nv_bfloat16* __restrict__ W0l,
    const __nv_bfloat16* __restrict__ W1h, const __nv_bfloat16* __restrict__ W1l,
    const float* __restrict__ b0, const float* __restrict__ b1,
    float* __restrict__ Cf, __nv_bfloat16* __restrict__ Ch, __nv_bfloat16* __restrict__ Cl,
    int mode)
{
    extern __shared__ __align__(16) char smem[];

    int tid = threadIdx.x, lane = tid & 31, wid = tid >> 5;
    int bid = blockIdx.x;
    int m0 = (bid >> 2) * 128, n0 = (bid & 3) * 128;   // n-fastest: A L2-resident

    const __nv_bfloat16 *Ah, *Al, *Wh, *Wl;
    const float* bb;
    int mb;
    if (m0 < splitM) { Ah = A0h; Al = A0l; Wh = W0h; Wl = W0l; bb = b0; mb = m0; }
    else             { Ah = A1h; Al = A1l; Wh = W1h; Wl = W1l; bb = b1; mb = m0 - splitM; }

    // staging: thread -> (row, half); copies 2x16B per tile, 4 tiles
    int srow = tid >> 1, half = tid & 1;
    const __nv_bfloat16* pAh = Ah + (size_t)(mb + srow) * D_ + half * 16;
    const __nv_bfloat16* pAl = Al + (size_t)(mb + srow) * D_ + half * 16;
    const __nv_bfloat16* pWh = Wh + (size_t)(n0 + srow) * D_ + half * 16;
    const __nv_bfloat16* pWl = Wl + (size_t)(n0 + srow) * D_ + half * 16;
    uint32_t dstoff = (uint32_t)srow * (ST_ * 2) + half * 32;

    int warpM = wid & 3, warpN = wid >> 2;
    int g = lane >> 2, c2 = (lane & 3) * 2;
    int aRowSel = lane & 15, aColSel = (lane >> 4) * 8;
    int bRowSel = (lane & 7) + (lane >> 4) * 8, bColSel = ((lane >> 3) & 1) * 8;

    float acc[2][8][4];
#pragma unroll
    for (int i = 0; i < 2; i++)
#pragma unroll
        for (int j = 0; j < 8; j++)
#pragma unroll
            for (int q = 0; q < 4; q++) acc[i][j][q] = 0.f;

    // prologue: stage slab 0
    {
        uint32_t d = smem_a32(smem + dstoff);
        cp16(d,              pAh);      cp16(d + 16,              pAh + 8);
        cp16(d + 10240,      pAl);      cp16(d + 10240 + 16,      pAl + 8);
        cp16(d + 20480,      pWh);      cp16(d + 20480 + 16,      pWh + 8);
        cp16(d + 30720,      pWl);      cp16(d + 30720 + 16,      pWl + 8);
        cp_commit();
        cp_wait0();
    }
    __syncthreads();

    for (int kt = 0; kt < 16; kt++) {
        char* cur = smem + (kt & 1) * STAGE_BYTES;
        // ---- stage next slab into other buffer (async) ----
        if (kt < 15) {
            int ko = (kt + 1) * 32;
            uint32_t d = smem_a32(smem + ((kt + 1) & 1) * STAGE_BYTES + dstoff);
            cp16(d,              pAh + ko); cp16(d + 16,              pAh + ko + 8);
            cp16(d + 10240,      pAl + ko); cp16(d + 10240 + 16,      pAl + ko + 8);
            cp16(d + 20480,      pWh + ko); cp16(d + 20480 + 16,      pWh + ko + 8);
            cp16(d + 30720,      pWl + ko); cp16(d + 30720 + 16,      pWl + ko + 8);
            cp_commit();
        }
        // ---- mma on current buffer ----
        char* sAh = cur;
        char* sAl = cur + 10240;
        char* sBh = cur + 20480;
        char* sBl = cur + 30720;
#pragma unroll
        for (int h = 0; h < 2; h++) {
            int ko = h * 16;
            uint32_t Af[2][4], Alf[2][4];
#pragma unroll
            for (int im = 0; im < 2; im++) {
                int r = warpM * 32 + im * 16;
                uint32_t offA = (uint32_t)(r + aRowSel) * (ST_ * 2) + (ko + aColSel) * 2;
                ldm_x4(Af[im], smem_a32(sAh + offA));
                ldm_x4(Alf[im], smem_a32(sAl + offA));
            }
#pragma unroll
            for (int p = 0; p < 4; p++) {
                int nr0 = warpN * 64 + p * 16;
                uint32_t offB = (uint32_t)(nr0 + bRowSel) * (ST_ * 2) + (ko + bColSel) * 2;
                uint32_t bh[4], bl[4];
                ldm_x4(bh, smem_a32(sBh + offB));
                ldm_x4(bl, smem_a32(sBl + offB));
#pragma unroll
                for (int s = 0; s < 2; s++) {
                    int in = 2 * p + s;
#pragma unroll
                    for (int im = 0; im < 2; im++) {
                        mma_bf16(acc[im][in], Af[im], bh[2 * s], bh[2 * s + 1]);
                        mma_bf16(acc[im][in], Af[im], bl[2 * s], bl[2 * s + 1]);
                        mma_bf16(acc[im][in], Alf[im], bh[2 * s], bh[2 * s + 1]);
                    }
                }
            }
        }
        if (kt < 15) cp_wait0();
        __syncthreads();
    }

    // ---- epilogue ----
#pragma unroll
    for (int im = 0; im < 2; im++) {
        int row0 = m0 + warpM * 32 + im * 16 + g;
#pragma unroll
        for (int in = 0; in < 8; in++) {
            int    col = n0 + warpN * 64 + in * 8 + c2;
            float2 bv  = *(const float2*)&bb[col];
            float  v0 = acc[im][in][0] + bv.x, v1 = acc[im][in][1] + bv.y;
            float  v2 = acc[im][in][2] + bv.x, v3 = acc[im][in][3] + bv.y;
            if (mode == 1) {
                v0 = gelu_tanh(v0); v1 = gelu_tanh(v1);
                v2 = gelu_tanh(v2); v3 = gelu_tanh(v3);
                __nv_bfloat162 h01, h23, l01, l23;
                h01.x = __float2bfloat16(v0); h01.y = __float2bfloat16(v1);
                h23.x = __float2bfloat16(v2); h23.y = __float2bfloat16(v3);
                l01.x = __float2bfloat16(v0 - __bfloat162float(h01.x));
                l01.y = __float2bfloat16(v1 - __bfloat162float(h01.y));
                l23.x = __float2bfloat16(v2 - __bfloat162float(h23.x));
                l23.y = __float2bfloat16(v3 - __bfloat162float(h23.y));
                *(__nv_bfloat162*)&Ch[(size_t)row0 * D_ + col]       = h01;
                *(__nv_bfloat162*)&Cl[(size_t)row0 * D_ + col]       = l01;
                *(__nv_bfloat162*)&Ch[(size_t)(row0 + 8) * D_ + col] = h23;
                *(__nv_bfloat162*)&Cl[(size_t)(row0 + 8) * D_ + col] = l23;
            } else {
                float2 w0; w0.x = v0; w0.y = v1;
                float2 w1; w1.x = v2; w1.y = v3;
                *(float2*)&Cf[(size_t)row0 * D_ + col]       = w0;
                *(float2*)&Cf[(size_t)(row0 + 8) * D_ + col] = w1;
            }
        }
    }
}

__global__ void l2norm_k(const float* __restrict__ V, float* __restrict__ out) {
    int w    = (blockIdx.x * blockDim.x + threadIdx.x) >> 5;
    int lane = threadIdx.x & 31;
    if (w >= 2 * B_) return;
    const float* p = V + (size_t)w * D_;
    float v[16];
    float s = 0.f;
#pragma unroll
    for (int i = 0; i < 16; i++) { v[i] = p[lane + 32 * i]; s = fmaf(v[i], v[i], s); }
#pragma unroll
    for (int o = 16; o; o >>= 1) s += __shfl_xor_sync(0xffffffffu, s, o);
    float inv = 1.0f / sqrtf(s);
#pragma unroll
    for (int i = 0; i < 16; i++) out[(size_t)w * D_ + lane + 32 * i] = v[i] * inv;
}

// ---------------------------------------------------------------------------
extern "C" void kernel_launch(void* const* d_in, const int* in_sizes, int n_in,
                              void* d_out, int out_size) {
    const float* image    = (const float*)d_in[0];
    const float* text     = (const float*)d_in[1];
    const float* wg_w1    = (const float*)d_in[2];
    const float* wg_b1    = (const float*)d_in[3];
    const float* wg_w2    = (const float*)d_in[4];
    const float* wg_b2    = (const float*)d_in[5];
    const float* conv_w   = (const float*)d_in[6];
    const float* conv_b   = (const float*)d_in[7];
    const float* mg_bn_g  = (const float*)d_in[8];
    const float* mg_bn_b  = (const float*)d_in[9];
    const float* mg_w     = (const float*)d_in[10];
    const float* mg_b     = (const float*)d_in[11];
    const float* ph_bn1_g = (const float*)d_in[12];
    const float* ph_bn1_b = (const float*)d_in[13];
    const float* ph_w1    = (const float*)d_in[14];
    const float* ph_b1    = (const float*)d_in[15];
    const float* ph_bn2_g = (const float*)d_in[16];
    const float* ph_bn2_b = (const float*)d_in[17];
    const float* ph_w2    = (const float*)d_in[18];
    const float* ph_b2    = (const float*)d_in[19];
    float*       out      = (float*)d_out;
    (void)in_sizes; (void)n_in; (void)out_size;

    __nv_bfloat16 *xh, *xl, *iah, *ial, *fh, *fl, *uh, *ul, *wh, *wl;
    float *pv, *pscl, *psft, *pbb;
    cudaGetSymbolAddress((void**)&xh, g_xh);   cudaGetSymbolAddress((void**)&xl, g_xl);
    cudaGetSymbolAddress((void**)&iah, g_iah); cudaGetSymbolAddress((void**)&ial, g_ial);
    cudaGetSymbolAddress((void**)&fh, g_fh);   cudaGetSymbolAddress((void**)&fl, g_fl);
    cudaGetSymbolAddress((void**)&uh, g_uh);   cudaGetSymbolAddress((void**)&ul, g_ul);
    cudaGetSymbolAddress((void**)&wh, g_wh);   cudaGetSymbolAddress((void**)&wl, g_wl);
    cudaGetSymbolAddress((void**)&pv, g_v);
    cudaGetSymbolAddress((void**)&pscl, g_scl);
    cudaGetSymbolAddress((void**)&psft, g_sft);
    cudaGetSymbolAddress((void**)&pbb, g_bb);

    cudaFuncSetAttribute(gemm_mma, cudaFuncAttributeMaxDynamicSharedMemorySize, GEMM_DSMEM);

    const float invB = 1.0f / (float)B_;
    const size_t WSZ = (size_t)D_ * D_;
    const size_t HALF = (size_t)B_ * D_;

    zero_stats_k<<<(5 * D_ + 255) / 256, 256>>>();
    split_k<<<B_ * D_ / 256, 256>>>(image, iah, ial);
    row_kernel<<<B_ / 8, 256>>>(image, text, wg_w1, wg_b1, wg_w2, wg_b2, conv_w, conv_b);

    colstats_k<<<256, 512>>>(image, B_, 0);
    colstats_hl<<<256, 512>>>(xh, xl, B_, 1);
    finalize_k<<<1, 512>>>(0, ph_bn1_g, ph_bn1_b, invB);
    finalize_k<<<1, 512>>>(1, mg_bn_g, mg_bn_b, invB);

    // slot 0: mg_w folded with set1
    wconv_k<<<D_ * D_ / 256, 256>>>(mg_w, pscl + 1 * D_, wh + 0 * WSZ, wl + 0 * WSZ);
    biasfix_k<<<1, 512>>>(mg_w, mg_b, psft + 1 * D_, pbb + 0 * D_);

    gemm_mma<<<(B_ / 128) * 4, 256, GEMM_DSMEM>>>(
        xh, xl, xh, xl, B_,
        wh + 0 * WSZ, wl + 0 * WSZ, wh + 0 * WSZ, wl + 0 * WSZ,
        pbb + 0 * D_, pbb + 0 * D_, nullptr, fh, fl, 1);

    colstats_hl<<<256, 512>>>(fh, fl, B_, 2);
    finalize_k<<<1, 512>>>(2, ph_bn1_g, ph_bn1_b, invB);

    // slots 1 (image/set0) and 2 (fused/set2) for ph_w1
    wconv_k<<<D_ * D_ / 256, 256>>>(ph_w1, pscl + 0 * D_, wh + 1 * WSZ, wl + 1 * WSZ);
    biasfix_k<<<1, 512>>>(ph_w1, ph_b1, psft + 0 * D_, pbb + 1 * D_);
    wconv_k<<<D_ * D_ / 256, 256>>>(ph_w1, pscl + 2 * D_, wh + 2 * WSZ, wl + 2 * WSZ);
    biasfix_k<<<1, 512>>>(ph_w1, ph_b1, psft + 2 * D_, pbb + 2 * D_);

    gemm_mma<<<(2 * B_ / 128) * 4, 256, GEMM_DSMEM>>>(
        iah, ial, fh, fl, B_,
        wh + 1 * WSZ, wl + 1 * WSZ, wh + 2 * WSZ, wl + 2 * WSZ,
        pbb + 1 * D_, pbb + 2 * D_, nullptr, uh, ul, 1);

    colstats_hl<<<256, 512>>>(uh, ul, B_, 3);
    colstats_hl<<<256, 512>>>(uh + HALF, ul + HALF, B_, 4);
    finalize_k<<<1, 512>>>(3, ph_bn2_g, ph_bn2_b, invB);
    finalize_k<<<1, 512>>>(4, ph_bn2_g, ph_bn2_b, invB);

    // slots 3 (u_img/set3) and 4 (u_fused/set4) for ph_w2
    wconv_k<<<D_ * D_ / 256, 256>>>(ph_w2, pscl + 3 * D_, wh + 3 * WSZ, wl + 3 * WSZ);
    biasfix_k<<<1, 512>>>(ph_w2, ph_b2, psft + 3 * D_, pbb + 3 * D_);
    wconv_k<<<D_ * D_ / 256, 256>>>(ph_w2, pscl + 4 * D_, wh + 4 * WSZ, wl + 4 * WSZ);
    biasfix_k<<<1, 512>>>(ph_w2, ph_b2, psft + 4 * D_, pbb + 4 * D_);

    gemm_mma<<<(2 * B_ / 128) * 4, 256, GEMM_DSMEM>>>(
        uh, ul, uh + HALF, ul + HALF, B_,
        wh + 3 * WSZ, wl + 3 * WSZ, wh + 4 * WSZ, wl + 4 * WSZ,
        pbb + 3 * D_, pbb + 4 * D_, pv, nullptr, nullptr, 0);

    l2norm_k<<<2 * B_ / 8, 256>>>(pv, out);
}

// round 17
// speedup vs baseline: 1.0912x; 1.0912x over previous
#include <cuda_runtime.h>
#include <cuda_fp16.h>
#include <cstdint>

#define B_ 16384
#define K_ 5
#define D_ 512
#define HG_ 16

// ---------------- scratch (static device globals; no allocs allowed) --------
__device__ float  g_x[B_ * D_];
__device__ float  g_fused[B_ * D_];
__device__ float  g_u[2 * B_ * D_];
__device__ float  g_v[2 * B_ * D_];
__device__ double g_sum[5 * D_];
__device__ double g_sq[5 * D_];
__device__ float  g_scl[5 * D_];
__device__ float  g_sft[5 * D_];
// W^T fp16 single, 3 slots: 0=mg_w 1=ph_w1 2=ph_w2   layout [n][k]
__device__ __half g_wt[3 * D_ * D_];

__device__ __forceinline__ float gelu_tanh(float x) {
    float x3 = x * x * x;
    float t  = tanhf(0.7978845608028654f * (x + 0.044715f * x3));
    return 0.5f * x * (1.0f + t);
}

// --- bitwise replication of XLA:CPU's vectorized f32 exp (Cephes expf) ------
__device__ __forceinline__ float xla_expf(float x) {
    float xx = fminf(fmaxf(x, -88.3762626647949f), 88.3762626647950f);
    float z  = floorf(__fadd_rn(__fmul_rn(1.44269504088896341f, xx), 0.5f));
    xx = __fsub_rn(xx, __fmul_rn(z, 0.693359375f));
    xx = __fsub_rn(xx, __fmul_rn(z, -2.12194440e-4f));
    float x2 = __fmul_rn(xx, xx);
    float y  = 1.9875691500E-4f;
    y = __fadd_rn(__fmul_rn(y, xx), 1.3981999507E-3f);
    y = __fadd_rn(__fmul_rn(y, xx), 8.3334519073E-3f);
    y = __fadd_rn(__fmul_rn(y, xx), 4.1665795894E-2f);
    y = __fadd_rn(__fmul_rn(y, xx), 1.6666665459E-1f);
    y = __fadd_rn(__fmul_rn(y, xx), 5.0000001201E-1f);
    y = __fadd_rn(__fmul_rn(y, x2), xx);
    y = __fadd_rn(y, 1.0f);
    return ldexpf(y, (int)z);
}
__device__ __forceinline__ float xla_sigmoid(float x) {
    return __fdiv_rn(1.0f, __fadd_rn(1.0f, xla_expf(-x)));
}

// mma.sync m16n8k16 fp16: D(f32) += A(f16,row) * B(f16,col)
__device__ __forceinline__ void mma_f16(float* d, const uint32_t* a,
                                        uint32_t b0, uint32_t b1) {
    asm volatile(
        "mma.sync.aligned.m16n8k16.row.col.f32.f16.f16.f32 "
        "{%0,%1,%2,%3}, {%4,%5,%6,%7}, {%8,%9}, {%0,%1,%2,%3};"
        : "+f"(d[0]), "+f"(d[1]), "+f"(d[2]), "+f"(d[3])
        : "r"(a[0]), "r"(a[1]), "r"(a[2]), "r"(a[3]), "r"(b0), "r"(b1));
}
__device__ __forceinline__ void ldm_x4(uint32_t* r, uint32_t addr) {
    asm volatile("ldmatrix.sync.aligned.m8n8.x4.shared.b16 {%0,%1,%2,%3}, [%4];"
                 : "=r"(r[0]), "=r"(r[1]), "=r"(r[2]), "=r"(r[3]) : "r"(addr));
}
__device__ __forceinline__ uint32_t smem_a32(const void* p) {
    return (uint32_t)__cvta_generic_to_shared(p);
}
__device__ __forceinline__ uint32_t pack_h2(float a, float b) {
    __half2 h = __halves2half2(__float2half_rn(a), __float2half_rn(b));
    return *reinterpret_cast<uint32_t*>(&h);
}

// ---------------------------------------------------------------------------
__global__ void zero_stats_k() {
    int i = blockIdx.x * blockDim.x + threadIdx.x;
    if (i < 5 * D_) { g_sum[i] = 0.0; g_sq[i] = 0.0; }
}

// W [k][n] fp32 -> W^T fp16 [n][k]
__global__ void wconv_k(const float* __restrict__ W, int slot) {
    int idx = blockIdx.x * blockDim.x + threadIdx.x;
    if (idx >= D_ * D_) return;
    int n = idx >> 9, k = idx & 511;
    g_wt[slot * D_ * D_ + idx] = __float2half_rn(W[k * D_ + n]);
}

__global__ void row_kernel(const float* __restrict__ img, const float* __restrict__ txt,
                           const float* __restrict__ w1, const float* __restrict__ b1,
                           const float* __restrict__ w2, const float* __restrict__ b2,
                           const float* __restrict__ cw, const float* __restrict__ cb)
{
    int w    = (blockIdx.x * blockDim.x + threadIdx.x) >> 5;
    int lane = threadIdx.x & 31;
    if (w >= B_) return;

    const float* ip = img + (size_t)w * D_;
    float  iv[16];
    double isq = 0.0;
#pragma unroll
    for (int i = 0; i < 16; i++) {
        iv[i] = ip[lane + 32 * i];
        isq += (double)iv[i] * (double)iv[i];
    }
#pragma unroll
    for (int o = 16; o; o >>= 1) isq += __shfl_xor_sync(0xffffffffu, isq, o);
    float inorm = fmaxf(sqrtf((float)isq), 1e-12f);

    float ivn[16];
#pragma unroll
    for (int i = 0; i < 16; i++) ivn[i] = __fdiv_rn(iv[i], inorm);

    float tv[K_][16];
    float sim[K_];
#pragma unroll
    for (int k = 0; k < K_; k++) {
        const float* tp = txt + ((size_t)w * K_ + k) * D_;
        double tsq = 0.0;
#pragma unroll
        for (int i = 0; i < 16; i++) {
            float t  = tp[lane + 32 * i];
            tv[k][i] = t;
            tsq += (double)t * (double)t;
        }
#pragma unroll
        for (int o = 16; o; o >>= 1) tsq += __shfl_xor_sync(0xffffffffu, tsq, o);
        float tnorm = fmaxf(sqrtf((float)tsq), 1e-12f);

        double dot = 0.0;
#pragma unroll
        for (int i = 0; i < 16; i++) {
            float tn = __fdiv_rn(tv[k][i], tnorm);
            dot += (double)__fmul_rn(ivn[i], tn);
        }
#pragma unroll
        for (int o = 16; o; o >>= 1) dot += __shfl_xor_sync(0xffffffffu, dot, o);
        sim[k] = (float)dot;
    }

    float wt[K_];
#pragma unroll
    for (int k = 0; k < K_; k++) {
        float acc = 0.0f;
#pragma unroll
        for (int j = 0; j < HG_; j++) {
            float h = fmaxf(__fadd_rn(__fmul_rn(sim[k], w1[j]), b1[j]), 0.0f);
            acc = __fadd_rn(acc, __fmul_rn(h, w2[j]));
        }
        acc   = __fadd_rn(acc, b2[0]);
        wt[k] = xla_sigmoid(acc);
    }

    float coef[K_];
#pragma unroll
    for (int p = 0; p < K_; p++) {
        int r = 0;
#pragma unroll
        for (int q = 0; q < K_; q++)
            r += (wt[q] > wt[p]) || (wt[q] == wt[p] && q < p);
        coef[p] = cw[r] * wt[p];
    }

    float  cbv = cb[0];
    float* xo  = g_x + (size_t)w * D_;
#pragma unroll
    for (int i = 0; i < 16; i++) {
        float s = cbv;
#pragma unroll
        for (int p = 0; p < K_; p++) s = fmaf(coef[p], tv[p][i], s);
        xo[lane + 32 * i] = s;
    }
}

__global__ void colstats_k(const float* __restrict__ A, int rows, int set) {
    int c     = threadIdx.x;
    int chunk = rows / gridDim.x;
    const float* p = A + (size_t)blockIdx.x * chunk * D_ + c;
    float s0 = 0.f, s1 = 0.f, q0 = 0.f, q1 = 0.f;
#pragma unroll 8
    for (int r = 0; r < chunk; r += 2) {
        float v0 = p[(size_t)r * D_];
        float v1 = p[(size_t)(r + 1) * D_];
        s0 += v0; q0 = fmaf(v0, v0, q0);
        s1 += v1; q1 = fmaf(v1, v1, q1);
    }
    atomicAdd(&g_sum[set * D_ + c], (double)(s0 + s1));
    atomicAdd(&g_sq[set * D_ + c], (double)(q0 + q1));
}

__global__ void finalize_k(int set, const float* __restrict__ g, const float* __restrict__ b,
                           float inv) {
    int   c    = threadIdx.x;
    float mean = (float)(g_sum[set * D_ + c] * inv);
    float ex2  = (float)(g_sq[set * D_ + c] * inv);
    float var  = ex2 - mean * mean;
    float sc   = g[c] * rsqrtf(var + 1e-5f);
    g_scl[set * D_ + c] = sc;
    g_sft[set * D_ + c] = b[c] - mean * sc;
}

// ---------------- tensor-core GEMM via mma.sync (fp16 A-split, 2 products) --
// C[m,n] = act( bn(A)[m,:] @ W + bias ),  W pre-transposed fp16 [n][k].
// CTA tile 128x128, 256 thr = 8 warps (4M x 2N), BK=32, single-buffer smem,
// ldmatrix operand loads. 1-D grid, n-fastest decode for A L2 reuse.
#define ST_ 40
__global__ __launch_bounds__(256) void gemm_mma(
    const float* __restrict__ A0, const float* __restrict__ A1, int splitM,
    int set0, int set1,
    const __half* __restrict__ wt,
    const float* __restrict__ bias, float* __restrict__ C, int doGelu)
{
    __shared__ __align__(16) char smem[3 * 128 * ST_ * 2];   // Ah Al B, 10240B each
    char* sAh = smem;
    char* sAl = smem + 10240;
    char* sB  = smem + 20480;

    int tid = threadIdx.x, lane = tid & 31, wid = tid >> 5;
    int bid = blockIdx.x;
    int m0 = (bid >> 2) * 128, n0 = (bid & 3) * 128;   // n-fastest: A tiles L2-resident

    const float *A, *scp, *shp;
    int mb;
    if (m0 < splitM) { A = A0; scp = g_scl + set0 * D_; shp = g_sft + set0 * D_; mb = m0; }
    else             { A = A1; scp = g_scl + set1 * D_; shp = g_sft + set1 * D_; mb = m0 - splitM; }

    int arow = tid >> 1, kh = (tid & 1) * 16;   // each thread: one tile row, 16 k's
    const float*  ap = A + (size_t)(mb + arow) * D_ + kh;
    const __half* bp = wt + (size_t)(n0 + arow) * D_ + kh;

    int warpM = wid & 3, warpN = wid >> 2;
    int g = lane >> 2, c2 = (lane & 3) * 2;

    // ldmatrix lane-address components
    int aRowSel = lane & 15, aColSel = (lane >> 4) * 8;                 // A x4
    int bRowSel = (lane & 7) + (lane >> 4) * 8, bColSel = ((lane >> 3) & 1) * 8; // B x4

    float acc[2][8][4];
#pragma unroll
    for (int i = 0; i < 2; i++)
#pragma unroll
        for (int j = 0; j < 8; j++)
#pragma unroll
            for (int q = 0; q < 4; q++) acc[i][j][q] = 0.f;

    // prefetch k-slab 0
    float4 af[4];
    uint4  pb0, pb1;
#pragma unroll
    for (int q = 0; q < 4; q++) af[q] = *(const float4*)(ap + q * 4);
    pb0 = *(const uint4*)(bp);
    pb1 = *(const uint4*)(bp + 8);

    for (int kt = 0; kt < 16; kt++) {
        int k0 = kt * 32;
        __syncthreads();   // previous slab fully consumed
        // ---- fold BN, fp16 split, store A; copy B ----
        {
            float x[16];
#pragma unroll
            for (int q = 0; q < 4; q++) {
                float4 s4 = *(const float4*)&scp[k0 + kh + q * 4];
                float4 h4 = *(const float4*)&shp[k0 + kh + q * 4];
                x[q * 4 + 0] = fmaf(af[q].x, s4.x, h4.x);
                x[q * 4 + 1] = fmaf(af[q].y, s4.y, h4.y);
                x[q * 4 + 2] = fmaf(af[q].z, s4.z, h4.z);
                x[q * 4 + 3] = fmaf(af[q].w, s4.w, h4.w);
            }
            uint32_t hp[8], lp[8];
#pragma unroll
            for (int j = 0; j < 8; j++) {
                float a0 = x[2 * j], a1 = x[2 * j + 1];
                __half h0 = __float2half_rn(a0), h1 = __float2half_rn(a1);
                __half2 hh = __halves2half2(h0, h1);
                hp[j] = *reinterpret_cast<uint32_t*>(&hh);
                lp[j] = pack_h2(a0 - __half2float(h0), a1 - __half2float(h1));
            }
            char* da = sAh + arow * (ST_ * 2) + kh * 2;
            *(uint4*)(da)      = *(uint4*)&hp[0];
            *(uint4*)(da + 16) = *(uint4*)&hp[4];
            char* dl = sAl + arow * (ST_ * 2) + kh * 2;
            *(uint4*)(dl)      = *(uint4*)&lp[0];
            *(uint4*)(dl + 16) = *(uint4*)&lp[4];
            char* db = sB + arow * (ST_ * 2) + kh * 2;
            *(uint4*)(db)      = pb0;
            *(uint4*)(db + 16) = pb1;
        }
        __syncthreads();
        // ---- prefetch next slab while mma runs ----
        if (kt < 15) {
#pragma unroll
            for (int q = 0; q < 4; q++) af[q] = *(const float4*)(ap + k0 + 32 + q * 4);
            pb0 = *(const uint4*)(bp + k0 + 32);
            pb1 = *(const uint4*)(bp + k0 + 40);
        }
        // ---- mma over two k16 halves, ldmatrix operands, 2 products ----
#pragma unroll
        for (int h = 0; h < 2; h++) {
            int ko = h * 16;
            uint32_t Af[2][4], Alf[2][4];
#pragma unroll
            for (int im = 0; im < 2; im++) {
                int r = warpM * 32 + im * 16;
                uint32_t offA = (uint32_t)(r + aRowSel) * (ST_ * 2) + (ko + aColSel) * 2;
                ldm_x4(Af[im], smem_a32(sAh + offA));
                ldm_x4(Alf[im], smem_a32(sAl + offA));
            }
#pragma unroll
            for (int p = 0; p < 4; p++) {
                int nr0 = warpN * 64 + p * 16;
                uint32_t offB = (uint32_t)(nr0 + bRowSel) * (ST_ * 2) + (ko + bColSel) * 2;
                uint32_t bf[4];
                ldm_x4(bf, smem_a32(sB + offB));
#pragma unroll
                for (int s = 0; s < 2; s++) {
                    int in = 2 * p + s;
#pragma unroll
                    for (int im = 0; im < 2; im++) {
                        mma_f16(acc[im][in], Af[im], bf[2 * s], bf[2 * s + 1]);
                        mma_f16(acc[im][in], Alf[im], bf[2 * s], bf[2 * s + 1]);
                    }
                }
            }
        }
    }

    // ---- epilogue: bias (+gelu), direct stores ----
#pragma unroll
    for (int im = 0; im < 2; im++) {
        int row0 = m0 + warpM * 32 + im * 16 + g;
#pragma unroll
        for (int in = 0; in < 8; in++) {
            int    col = n0 + warpN * 64 + in * 8 + c2;
            float2 bb  = *(const float2*)&bias[col];
            float  v0 = acc[im][in][0] + bb.x, v1 = acc[im][in][1] + bb.y;
            float  v2 = acc[im][in][2] + bb.x, v3 = acc[im][in][3] + bb.y;
            if (doGelu) {
                v0 = gelu_tanh(v0); v1 = gelu_tanh(v1);
                v2 = gelu_tanh(v2); v3 = gelu_tanh(v3);
            }
            float2 w0; w0.x = v0; w0.y = v1;
            float2 w1; w1.x = v2; w1.y = v3;
            *(float2*)&C[(size_t)row0 * D_ + col]       = w0;
            *(float2*)&C[(size_t)(row0 + 8) * D_ + col] = w1;
        }
    }
}

__global__ void l2norm_k(const float* __restrict__ V, float* __restrict__ out) {
    int w    = (blockIdx.x * blockDim.x + threadIdx.x) >> 5;
    int lane = threadIdx.x & 31;
    if (w >= 2 * B_) return;
    const float* p = V + (size_t)w * D_;
    float v[16];
    float s = 0.f;
#pragma unroll
    for (int i = 0; i < 16; i++) { v[i] = p[lane + 32 * i]; s = fmaf(v[i], v[i], s); }
#pragma unroll
    for (int o = 16; o; o >>= 1) s += __shfl_xor_sync(0xffffffffu, s, o);
    float inv = 1.0f / sqrtf(s);
#pragma unroll
    for (int i = 0; i < 16; i++) out[(size_t)w * D_ + lane + 32 * i] = v[i] * inv;
}

// ---------------------------------------------------------------------------
extern "C" void kernel_launch(void* const* d_in, const int* in_sizes, int n_in,
                              void* d_out, int out_size) {
    const float* image    = (const float*)d_in[0];
    const float* text     = (const float*)d_in[1];
    const float* wg_w1    = (const float*)d_in[2];
    const float* wg_b1    = (const float*)d_in[3];
    const float* wg_w2    = (const float*)d_in[4];
    const float* wg_b2    = (const float*)d_in[5];
    const float* conv_w   = (const float*)d_in[6];
    const float* conv_b   = (const float*)d_in[7];
    const float* mg_bn_g  = (const float*)d_in[8];
    const float* mg_bn_b  = (const float*)d_in[9];
    const float* mg_w     = (const float*)d_in[10];
    const float* mg_b     = (const float*)d_in[11];
    const float* ph_bn1_g = (const float*)d_in[12];
    const float* ph_bn1_b = (const float*)d_in[13];
    const float* ph_w1    = (const float*)d_in[14];
    const float* ph_b1    = (const float*)d_in[15];
    const float* ph_bn2_g = (const float*)d_in[16];
    const float* ph_bn2_b = (const float*)d_in[17];
    const float* ph_w2    = (const float*)d_in[18];
    const float* ph_b2    = (const float*)d_in[19];
    float*       out      = (float*)d_out;
    (void)in_sizes; (void)n_in; (void)out_size;

    float *px, *pf, *pu, *pv;
    __half* pwt;
    cudaGetSymbolAddress((void**)&px, g_x);
    cudaGetSymbolAddress((void**)&pf, g_fused);
    cudaGetSymbolAddress((void**)&pu, g_u);
    cudaGetSymbolAddress((void**)&pv, g_v);
    cudaGetSymbolAddress((void**)&pwt, g_wt);

    const float invB = 1.0f / (float)B_;
    const size_t WSZ = (size_t)D_ * D_;
    const size_t HALF = (size_t)B_ * D_;

    zero_stats_k<<<(5 * D_ + 255) / 256, 256>>>();
    wconv_k<<<D_ * D_ / 256, 256>>>(mg_w, 0);
    wconv_k<<<D_ * D_ / 256, 256>>>(ph_w1, 1);
    wconv_k<<<D_ * D_ / 256, 256>>>(ph_w2, 2);
    row_kernel<<<B_ / 8, 256>>>(image, text, wg_w1, wg_b1, wg_w2, wg_b2, conv_w, conv_b);

    colstats_k<<<256, 512>>>(image, B_, 0);
    colstats_k<<<256, 512>>>(px, B_, 1);
    finalize_k<<<1, 512>>>(0, ph_bn1_g, ph_bn1_b, invB);
    finalize_k<<<1, 512>>>(1, mg_bn_g, mg_bn_b, invB);

    gemm_mma<<<(B_ / 128) * 4, 256>>>(px, nullptr, B_, 1, 1,
                                      pwt + 0 * WSZ, mg_b, pf, 1);

    colstats_k<<<256, 512>>>(pf, B_, 2);
    finalize_k<<<1, 512>>>(2, ph_bn1_g, ph_bn1_b, invB);

    gemm_mma<<<(2 * B_ / 128) * 4, 256>>>(image, pf, B_, 0, 2,
                                          pwt + 1 * WSZ, ph_b1, pu, 1);

    colstats_k<<<256, 512>>>(pu, B_, 3);
    colstats_k<<<256, 512>>>(pu + HALF, B_, 4);
    finalize_k<<<1, 512>>>(3, ph_bn2_g, ph_bn2_b, invB);
    finalize_k<<<1, 512>>>(4, ph_bn2_g, ph_bn2_b, invB);

    gemm_mma<<<(2 * B_ / 128) * 4, 256>>>(pu, pu + HALF, B_, 3, 4,
                                          pwt + 2 * WSZ, ph_b2, pv, 0);

    l2norm_k<<<2 * B_ / 8, 256>>>(pv, out);
}